// round 13
// baseline (speedup 1.0000x reference)
#include <cuda_runtime.h>

typedef unsigned long long ull;
typedef unsigned int uint;
typedef unsigned short ushort;

#define NB 4
#define NPTS 8192
#define ND 64
#define NSP 2048
#define NK 16
#define NSAMP (NB*NSP*NK)          // 131072
#define LEAKY 0.1f
#define FULLM 0xffffffffu

#define OUT_XYZ_OFF 0
#define OUT_FEAT_OFF (NB*3*NSP)                 // 24576
#define OUT_FPS_OFF (OUT_FEAT_OFF + NB*128*NSP) // 1073152

// ---------------- scratch (static __device__, allocation-free) ----------------
__device__ float g_pts_t[(size_t)NB*NPTS*ND];   // [b][n][d]   8.4 MB
__device__ float g_sdst[NB*NPTS];               // |p|^2 per point
__device__ float g_newxyz[NB*NSP*3];            // centroids [bs][3]
__device__ uint  g_perm[NB][NPTS];              // spatially-binned point order
__device__ int   g_knn[NB*NSP*NK];              // neighbor indices
__device__ float g_y0[(size_t)64*NSAMP];        // channel-major [c][sample]
__device__ float g_y1[(size_t)64*NSAMP];
__device__ float g_y2[(size_t)128*NSAMP];
__device__ double g_sum[3*128];
__device__ double g_sq[3*128];
__device__ float g_scale[3*128];
__device__ float g_bias[3*128];

// ---------------- packed f32x2 helpers (sm_103a; ptxas won't auto-emit) ------
__device__ __forceinline__ ull addx2(ull a, ull b) {
    ull r; asm("add.rn.f32x2 %0, %1, %2;" : "=l"(r) : "l"(a), "l"(b)); return r;
}
__device__ __forceinline__ ull mulx2(ull a, ull b) {
    ull r; asm("mul.rn.f32x2 %0, %1, %2;" : "=l"(r) : "l"(a), "l"(b)); return r;
}
__device__ __forceinline__ ull packx2(float lo, float hi) {
    ull r; asm("mov.b64 %0, {%1, %2};" : "=l"(r) : "f"(lo), "f"(hi)); return r;
}
__device__ __forceinline__ void unpackx2(float& lo, float& hi, ull v) {
    asm("mov.b64 {%0, %1}, %2;" : "=f"(lo), "=f"(hi) : "l"(v));
}

// ---------------- zero the BN accumulators (ALL 384 of each!) ----------------
__global__ void k_zero() {
    int i = threadIdx.x;
    if (i < 384) { g_sum[i] = 0.0; g_sq[i] = 0.0; }
}

// ---------------- transpose points + precompute |p|^2 ----------------
__global__ void k_prep(const float* __restrict__ xyz, const float* __restrict__ pts) {
    int idx = blockIdx.x * blockDim.x + threadIdx.x;   // NB*NPTS
    int b = idx >> 13;
    int n = idx & (NPTS - 1);
    const float* xb = xyz + (size_t)b * 3 * NPTS;
    float x = xb[n], y = xb[NPTS + n], z = xb[2 * NPTS + n];
    g_sdst[idx] = __fadd_rn(__fadd_rn(__fmul_rn(x, x), __fmul_rn(y, y)), __fmul_rn(z, z));
    const float* pb = pts + (size_t)b * ND * NPTS;
    float4* dst = (float4*)(g_pts_t + (size_t)idx * ND);
#pragma unroll
    for (int dg = 0; dg < ND / 4; ++dg) {
        float4 v;
        v.x = pb[(dg * 4 + 0) * NPTS + n];
        v.y = pb[(dg * 4 + 1) * NPTS + n];
        v.z = pb[(dg * 4 + 2) * NPTS + n];
        v.w = pb[(dg * 4 + 3) * NPTS + n];
        dst[dg] = v;
    }
}

// ---------------- spatial binning: counting sort by 9-bit Morton cell --------
// Order within a cell is atomic-nondeterministic; this only changes WHICH
// provably-no-op work fps skips, never any output value.
__device__ __forceinline__ uint exp3(uint v) {   // 3 bits -> bits 0,3,6
    return (v & 1u) | ((v & 2u) << 2) | ((v & 4u) << 4);
}

__global__ void __launch_bounds__(1024) k_bin(const float* __restrict__ xyz) {
    __shared__ uint hist[512];
    __shared__ uint wsum[16];
    __shared__ ushort cellid[NPTS];
    const int b = blockIdx.x;
    const int tid = threadIdx.x;
    const int lane = tid & 31;
    const float* xb = xyz + (size_t)b * 3 * NPTS;

    if (tid < 512) hist[tid] = 0u;
    __syncthreads();
#pragma unroll
    for (int j = 0; j < 8; ++j) {
        int n = j * 1024 + tid;
        uint qx = (uint)max(0, min(7, (int)(xb[n] + 4.0f)));
        uint qy = (uint)max(0, min(7, (int)(xb[NPTS + n] + 4.0f)));
        uint qz = (uint)max(0, min(7, (int)(xb[2 * NPTS + n] + 4.0f)));
        uint code = (exp3(qx) << 2) | (exp3(qy) << 1) | exp3(qz);
        cellid[n] = (ushort)code;
        atomicAdd(&hist[code], 1u);
    }
    __syncthreads();
    // exclusive scan of 512 bins
    uint v = 0, inc = 0;
    if (tid < 512) { v = hist[tid]; inc = v; }
#pragma unroll
    for (int off = 1; off < 32; off <<= 1) {
        uint o = __shfl_up_sync(FULLM, inc, off);
        if (lane >= off) inc += o;
    }
    if (tid < 512 && lane == 31) wsum[tid >> 5] = inc;
    __syncthreads();
    if (tid == 0) {
        uint run = 0;
        for (int i = 0; i < 16; ++i) { uint t2 = wsum[i]; wsum[i] = run; run += t2; }
    }
    __syncthreads();
    uint excl = 0;
    if (tid < 512) excl = inc - v + wsum[tid >> 5];
    __syncthreads();
    if (tid < 512) hist[tid] = excl;
    __syncthreads();
#pragma unroll
    for (int j = 0; j < 8; ++j) {
        int n = j * 1024 + tid;
        uint pos = atomicAdd(&hist[cellid[n]], 1u);
        g_perm[b][pos] = (uint)n;
    }
}

// ---------------- fps: 1024 thr, 8 binned pts/thread, warp-uniform pruning ----
// Exact vs jax scan: seed 0; dist=min(dist,|p-c|^2) with (dx*dx+dy*dy)+dz*dz
// rounding order; next=argmax first-max-on-ties. Warp chunk = 256 binned pts
// (sphere cc,R identical in all lanes -> uniform branch). Skip iff
// ddsq*0.998 >= T=(sqrt(M)*1.001+R)^2*1.002, proving d(p,c)^2 >= M >= dist[p]
// for all chunk points -> dists AND cached candidate kcache=(M,comp) unchanged.
// Skipped iters bypass math, redux AND comp scan; one barrier/iter via
// double-buffered exchange. Indices live in shared (register budget < 64).
__global__ void __launch_bounds__(1024, 1) k_fps(const float* __restrict__ xyz,
                                                 float* __restrict__ out) {
    extern __shared__ char fsm[];
    ull* wk = (ull*)fsm;                        // [2][32] double-buffered
    float* sx = (float*)(fsm + 512);
    float* sy = sx + NPTS;
    float* sz = sy + NPTS;
    ushort* sperm = (ushort*)(sz + NPTS);

    const int b = blockIdx.x;
    const int tid = threadIdx.x;
    const int lane = tid & 31;
    const int warp = tid >> 5;
    const float* xb = xyz + (size_t)b * 3 * NPTS;

#pragma unroll
    for (int j = 0; j < 8; ++j) {
        int n = j * 1024 + tid;
        sx[n] = xb[n]; sy[n] = xb[NPTS + n]; sz[n] = xb[2 * NPTS + n];
        sperm[n] = (ushort)g_perm[b][n];
    }
    __syncthreads();

    ull px2[4], py2[4], pz2[4];
    float dist[8];
    float ccx, ccy, ccz, R;
    {
        float px[8], py[8], pz[8];
        float sxx = 0.f, syy = 0.f, szz = 0.f;
#pragma unroll
        for (int jj = 0; jj < 8; ++jj) {
            uint o = sperm[tid * 8 + jj];
            px[jj] = sx[o]; py[jj] = sy[o]; pz[jj] = sz[o];
            sxx += px[jj]; syy += py[jj]; szz += pz[jj];
            dist[jj] = 1e10f;
        }
#pragma unroll
        for (int off = 16; off > 0; off >>= 1) {
            sxx += __shfl_xor_sync(FULLM, sxx, off);
            syy += __shfl_xor_sync(FULLM, syy, off);
            szz += __shfl_xor_sync(FULLM, szz, off);
        }
        ccx = sxx * (1.0f / 256.0f);
        ccy = syy * (1.0f / 256.0f);
        ccz = szz * (1.0f / 256.0f);
        float mr2 = 0.f;
#pragma unroll
        for (int jj = 0; jj < 8; ++jj) {
            float dx = px[jj] - ccx, dy = py[jj] - ccy, dz = pz[jj] - ccz;
            mr2 = fmaxf(mr2, dx * dx + dy * dy + dz * dz);
        }
#pragma unroll
        for (int off = 16; off > 0; off >>= 1)
            mr2 = fmaxf(mr2, __shfl_xor_sync(FULLM, mr2, off));
        R = __fsqrt_rn(mr2) * 1.001f + 1e-6f;
#pragma unroll
        for (int k = 0; k < 4; ++k) {
            px2[k] = packx2(px[2 * k], px[2 * k + 1]);
            py2[k] = packx2(py[2 * k], py[2 * k + 1]);
            pz2[k] = packx2(pz[2 * k], pz[2 * k + 1]);
        }
    }

    ull kcache = 0;
    float T = 3.4e38f;             // t=0 fully active -> caches become real
    int cur = 0;
    for (int t = 0; t < NSP; ++t) {
        float cx = sx[cur], cy = sy[cur], cz = sz[cur];
        if (tid == 0) {
            out[OUT_FPS_OFF + b * NSP + t] = (float)cur;
            g_newxyz[(b * NSP + t) * 3 + 0] = cx;
            g_newxyz[(b * NSP + t) * 3 + 1] = cy;
            g_newxyz[(b * NSP + t) * 3 + 2] = cz;
            out[OUT_XYZ_OFF + b * 3 * NSP + 0 * NSP + t] = cx;
            out[OUT_XYZ_OFF + b * 3 * NSP + 1 * NSP + t] = cy;
            out[OUT_XYZ_OFF + b * 3 * NSP + 2 * NSP + t] = cz;
        }
        if (t == NSP - 1) break;

        float ex = ccx - cx, ey = ccy - cy, ez = ccz - cz;
        float ddsq = fmaf(ex, ex, fmaf(ey, ey, ez * ez));
        if (ddsq * 0.998f < T) {                  // warp-uniform active branch
            const ull ncx2 = packx2(-cx, -cx);    // p-c == p+(-c), negation exact
            const ull ncy2 = packx2(-cy, -cy);
            const ull ncz2 = packx2(-cz, -cz);
            float maxv = -1.0f;
#pragma unroll
            for (int k = 0; k < 4; ++k) {
                ull dx2 = addx2(px2[k], ncx2);
                ull dy2 = addx2(py2[k], ncy2);
                ull dz2 = addx2(pz2[k], ncz2);
                ull m0 = mulx2(dx2, dx2);
                ull m1 = mulx2(dy2, dy2);
                ull m2 = mulx2(dz2, dz2);
                ull s = addx2(addx2(m0, m1), m2);   // reference rounding order
                float dlo, dhi;
                unpackx2(dlo, dhi, s);
                float a = fminf(dist[2 * k], dlo);
                dist[2 * k] = a;
                maxv = fmaxf(maxv, a);
                float c2 = fminf(dist[2 * k + 1], dhi);
                dist[2 * k + 1] = c2;
                maxv = fmaxf(maxv, c2);
            }
            uint bb = __float_as_uint(maxv);      // dist>=0: bits order-monotone
            uint wmax = __reduce_max_sync(FULLM, bb);
            uint comp = 0u;
            if (bb == wmax) {                     // only warp-max lanes scan
                float gb = __uint_as_float(wmax); // exact: fmin/fmax return inputs
#pragma unroll
                for (int jj = 0; jj < 8; ++jj)
                    if (dist[jj] == gb)
                        comp = max(comp, FULLM - (uint)sperm[tid * 8 + jj]);
            }
            uint wcomp = __reduce_max_sync(FULLM, comp);
            kcache = ((ull)wmax << 32) | wcomp;
            float sq = __fsqrt_rn(__uint_as_float(wmax)) * 1.001f + R;
            T = sq * sq * 1.002f;
        }

        if (lane == 0) wk[(t & 1) * 32 + warp] = kcache;
        __syncthreads();
        ull e = wk[(t & 1) * 32 + lane];
        uint hi = (uint)(e >> 32), lo = (uint)e;
        uint ghi = __reduce_max_sync(FULLM, hi);
        uint glo = __reduce_max_sync(FULLM, (hi == ghi) ? lo : 0u);
        cur = (int)(FULLM - glo);
    }
}

// ---------------- kNN: one warp per (b,s), warp-shared sorted top-16 ----------
// (R7 variant, measured 107-113us)
__device__ __forceinline__ uint sortable(float v) {
    uint u = __float_as_uint(v);
    return (u & 0x80000000u) ? ~u : (u | 0x80000000u);
}

__global__ void __launch_bounds__(256) k_knn(const float* __restrict__ xyz) {
    const int lane = threadIdx.x & 31;
    const int w = threadIdx.x >> 5;
    const int gw = blockIdx.x * 8 + w;   // 0 .. NB*NSP-1
    const int b = gw >> 11;
    const int bs = gw;

    float cx = g_newxyz[bs * 3 + 0];
    float cy = g_newxyz[bs * 3 + 1];
    float cz = g_newxyz[bs * 3 + 2];
    float ssrc = __fadd_rn(__fadd_rn(__fmul_rn(cx, cx), __fmul_rn(cy, cy)),
                           __fmul_rn(cz, cz));

    const float* xb = xyz + (size_t)b * 3 * NPTS;
    const float4* x4 = (const float4*)xb;
    const float4* y4 = (const float4*)(xb + NPTS);
    const float4* z4 = (const float4*)(xb + 2 * NPTS);
    const float4* s4 = (const float4*)(g_sdst + b * NPTS);

    ull L = ~0ull;                 // lanes 0..15: sorted ascending top-16
    uint tauhi = 0xFFFFFFFFu;      // hi32 of L[15]

    for (int gidx = lane; gidx < NPTS / 4; gidx += 32) {   // 64 uniform steps
        float4 X = x4[gidx], Y = y4[gidx], Z = z4[gidx], S = s4[gidx];
        const float pxa[4] = {X.x, X.y, X.z, X.w};
        const float pya[4] = {Y.x, Y.y, Y.z, Y.w};
        const float pza[4] = {Z.x, Z.y, Z.z, Z.w};
        const float sda[4] = {S.x, S.y, S.z, S.w};
        uint sa[4];
#pragma unroll
        for (int q = 0; q < 4; ++q) {
            float dot = fmaf(cz, pza[q], fmaf(cy, pya[q], cx * pxa[q]));
            float v = fmaf(-2.0f, dot, ssrc);    // exact: -2*dot has no rounding
            v = __fadd_rn(v, sda[q]);
            sa[q] = sortable(v);
        }
#pragma unroll
        for (int q = 0; q < 4; ++q) {
            uint pass = __ballot_sync(FULLM, sa[q] <= tauhi);
            while (pass) {
                const int src = __ffs(pass) - 1;
                pass &= pass - 1;
                uint shi = __shfl_sync(FULLM, sa[q], src);
                uint sgi = (uint)__shfl_sync(FULLM, gidx, src);
                ull key = ((ull)shi << 32) | (sgi * 4 + q);
                ull l15 = __shfl_sync(FULLM, L, 15);
                if (key < l15) {                 // exact recheck (ties by index)
                    ull v = (lane < 16) ? L : ~0ull;
                    uint pos = __popc(__ballot_sync(FULLM, v < key));
                    ull vup = __shfl_up_sync(FULLM, L, 1);
                    ull nv = (lane < (int)pos) ? L : ((lane == (int)pos) ? key : vup);
                    if (lane < 16) L = nv;
                    tauhi = (uint)(__shfl_sync(FULLM, L, 15) >> 32);
                }
            }
        }
    }
    if (lane < NK) g_knn[bs * NK + lane] = (int)(L & 0xFFFFFFFFu);
}

// ---------------- conv0: gather(67ch) -> 64ch GEMM + BN partials ----------------
__global__ void __launch_bounds__(128) k_conv0(const float* __restrict__ xyz,
                                               const float* __restrict__ w0) {
    __shared__ float Xs[67 * 64];
    __shared__ float Ws[67 * 64];
    __shared__ int   n_sh[64];
    __shared__ float ps[64], pq[64];

    const int tid = threadIdx.x;
    const int s0 = blockIdx.x * 64;          // first sample of this block
    const int b = blockIdx.x >> 9;           // 512 blocks per batch (uniform)
    const float* xb = xyz + (size_t)b * 3 * NPTS;

    if (tid < 64) { ps[tid] = 0.0f; pq[tid] = 0.0f; }

    for (int i = tid; i < 64 * 67; i += 128) {
        int o = i / 67, c = i - o * 67;
        Ws[c * 64 + o] = w0[i];
    }
    if (tid < 64) {
        int samp = s0 + tid;
        int bs = samp >> 4, k = samp & 15;
        int n = g_knn[bs * NK + k];
        n_sh[tid] = n;
        float cx = g_newxyz[bs * 3 + 0];
        float cy = g_newxyz[bs * 3 + 1];
        float cz = g_newxyz[bs * 3 + 2];
        Xs[0 * 64 + tid] = xb[n] - cx;
        Xs[1 * 64 + tid] = xb[NPTS + n] - cy;
        Xs[2 * 64 + tid] = xb[2 * NPTS + n] - cz;
    }
    __syncthreads();
    for (int ci = tid; ci < 64 * 16; ci += 128) {
        int m = ci & 63, dg = ci >> 6;
        int n = n_sh[m];
        float4 v = *(const float4*)(g_pts_t + ((size_t)(b * NPTS + n) * ND + dg * 4));
        Xs[(3 + dg * 4 + 0) * 64 + m] = v.x;
        Xs[(3 + dg * 4 + 1) * 64 + m] = v.y;
        Xs[(3 + dg * 4 + 2) * 64 + m] = v.z;
        Xs[(3 + dg * 4 + 3) * 64 + m] = v.w;
    }
    __syncthreads();

    const int sg = tid & 15;     // 4 samples
    const int og = tid >> 4;     // 8 outputs
    float acc[4][8];
#pragma unroll
    for (int i = 0; i < 4; ++i)
#pragma unroll
        for (int j = 0; j < 8; ++j) acc[i][j] = 0.0f;

    const float4* Xs4 = (const float4*)Xs;
    const float4* Ws4 = (const float4*)Ws;
#pragma unroll 4
    for (int c = 0; c < 67; ++c) {
        float4 xv = Xs4[c * 16 + sg];
        float4 wa = Ws4[c * 16 + og * 2];
        float4 wb = Ws4[c * 16 + og * 2 + 1];
        float xs[4] = {xv.x, xv.y, xv.z, xv.w};
        float ws[8] = {wa.x, wa.y, wa.z, wa.w, wb.x, wb.y, wb.z, wb.w};
#pragma unroll
        for (int i = 0; i < 4; ++i)
#pragma unroll
            for (int j = 0; j < 8; ++j) acc[i][j] = fmaf(xs[i], ws[j], acc[i][j]);
    }
#pragma unroll
    for (int j = 0; j < 8; ++j) {
        float4 v = make_float4(acc[0][j], acc[1][j], acc[2][j], acc[3][j]);
        *(float4*)&g_y0[(size_t)(og * 8 + j) * NSAMP + s0 + sg * 4] = v;
        float su = acc[0][j] + acc[1][j] + acc[2][j] + acc[3][j];
        float qu = acc[0][j] * acc[0][j] + acc[1][j] * acc[1][j] +
                   acc[2][j] * acc[2][j] + acc[3][j] * acc[3][j];
        atomicAdd(&ps[og * 8 + j], su);
        atomicAdd(&pq[og * 8 + j], qu);
    }
    __syncthreads();
    if (tid < 64) {
        atomicAdd(&g_sum[0 * 128 + tid], (double)ps[tid]);
        atomicAdd(&g_sq[0 * 128 + tid], (double)pq[tid]);
    }
}

// ---------------- BN stats -> fused scale/bias ----------------
__global__ void k_stats(int st, int cout, const float* __restrict__ gamma,
                        const float* __restrict__ beta) {
    int c = threadIdx.x;
    if (c < cout) {
        double n = (double)NSAMP;
        double mean = g_sum[st * 128 + c] / n;
        double var = g_sq[st * 128 + c] / n - mean * mean;
        double rstd = 1.0 / sqrt(var + 1e-5);
        double sc = (double)gamma[c] * rstd;
        g_scale[st * 128 + c] = (float)sc;
        g_bias[st * 128 + c] = (float)((double)beta[c] - mean * sc);
    }
}

// ---------------- conv1 / conv2: act(BN prev) -> GEMM + BN partials ----------------
template <int LAYER>
__global__ void __launch_bounds__((LAYER == 1) ? 128 : 256)
k_conv(const float* __restrict__ w) {
    constexpr int COUT = (LAYER == 1) ? 64 : 128;
    constexpr int ST_IN = LAYER - 1;
    constexpr int ST_OUT = LAYER;
    const float* yin = (LAYER == 1) ? g_y0 : g_y1;
    float* yout = (LAYER == 1) ? g_y1 : g_y2;

    extern __shared__ float shm[];
    float* Xs = shm;                 // 64*64
    float* Ws = Xs + 64 * 64;        // 64*COUT
    float* ps = Ws + 64 * COUT;
    float* pq = ps + COUT;

    const int tid = threadIdx.x;
    constexpr int NTHR = (COUT / 8) * 16;
    const int s0 = blockIdx.x * 64;

    for (int c = tid; c < COUT; c += NTHR) { ps[c] = 0.0f; pq[c] = 0.0f; }
    for (int i = tid; i < 64 * COUT; i += NTHR) {
        int o = i >> 6, c = i & 63;
        Ws[c * COUT + o] = w[i];
    }
    const float* sc = g_scale + ST_IN * 128;
    const float* bi = g_bias + ST_IN * 128;
    for (int i = tid; i < 64 * 64; i += NTHR) {
        int m = i & 63, c = i >> 6;
        float v = yin[(size_t)c * NSAMP + s0 + m];
        v = fmaf(v, sc[c], bi[c]);
        v = (v > 0.0f) ? v : LEAKY * v;
        Xs[c * 64 + m] = v;
    }
    __syncthreads();

    const int sg = tid & 15;
    const int og = tid >> 4;
    float acc[4][8];
#pragma unroll
    for (int i = 0; i < 4; ++i)
#pragma unroll
        for (int j = 0; j < 8; ++j) acc[i][j] = 0.0f;

    const float4* Xs4 = (const float4*)Xs;
    const float4* Ws4 = (const float4*)Ws;
#pragma unroll 4
    for (int c = 0; c < 64; ++c) {
        float4 xv = Xs4[c * 16 + sg];
        float4 wa = Ws4[c * (COUT / 4) + og * 2];
        float4 wb = Ws4[c * (COUT / 4) + og * 2 + 1];
        float xs[4] = {xv.x, xv.y, xv.z, xv.w};
        float ws[8] = {wa.x, wa.y, wa.z, wa.w, wb.x, wb.y, wb.z, wb.w};
#pragma unroll
        for (int i = 0; i < 4; ++i)
#pragma unroll
            for (int j = 0; j < 8; ++j) acc[i][j] = fmaf(xs[i], ws[j], acc[i][j]);
    }
#pragma unroll
    for (int j = 0; j < 8; ++j) {
        float4 v = make_float4(acc[0][j], acc[1][j], acc[2][j], acc[3][j]);
        *(float4*)&yout[(size_t)(og * 8 + j) * NSAMP + s0 + sg * 4] = v;
        float su = acc[0][j] + acc[1][j] + acc[2][j] + acc[3][j];
        float qu = acc[0][j] * acc[0][j] + acc[1][j] * acc[1][j] +
                   acc[2][j] * acc[2][j] + acc[3][j] * acc[3][j];
        atomicAdd(&ps[og * 8 + j], su);
        atomicAdd(&pq[og * 8 + j], qu);
    }
    __syncthreads();
    for (int c = tid; c < COUT; c += NTHR) {
        atomicAdd(&g_sum[ST_OUT * 128 + c], (double)ps[c]);
        atomicAdd(&g_sq[ST_OUT * 128 + c], (double)pq[c]);
    }
}

// ---------------- final: act(BN2) + max over K ----------------
__global__ void __launch_bounds__(256) k_final(float* __restrict__ out) {
    const int lane = threadIdx.x & 31;
    const int gw = (blockIdx.x * blockDim.x + threadIdx.x) >> 5;  // bs index
    const int b = gw >> 11;
    const int s = gw & 2047;
    const float* sc = g_scale + 2 * 128;
    const float* bi = g_bias + 2 * 128;
#pragma unroll
    for (int j = 0; j < 4; ++j) {
        int o = lane + 32 * j;
        const float4* row = (const float4*)(g_y2 + (size_t)o * NSAMP + gw * NK);
        float scv = sc[o], biv = bi[o];
        float m = -3.4e38f;
#pragma unroll
        for (int q = 0; q < 4; ++q) {
            float4 v4 = row[q];
            float vv[4] = {v4.x, v4.y, v4.z, v4.w};
#pragma unroll
            for (int r = 0; r < 4; ++r) {
                float v = fmaf(vv[r], scv, biv);
                v = (v > 0.0f) ? v : LEAKY * v;
                m = fmaxf(m, v);
            }
        }
        out[OUT_FEAT_OFF + ((size_t)b * 128 + o) * NSP + s] = m;
    }
}

// ---------------- launch ----------------
extern "C" void kernel_launch(void* const* d_in, const int* in_sizes, int n_in,
                              void* d_out, int out_size) {
    (void)in_sizes; (void)n_in; (void)out_size;
    const float* xyz = (const float*)d_in[0];
    const float* pts = (const float*)d_in[1];
    const float* w0 = (const float*)d_in[2];
    const float* w1 = (const float*)d_in[3];
    const float* w2 = (const float*)d_in[4];
    const float* g0 = (const float*)d_in[5];
    const float* b0 = (const float*)d_in[6];
    const float* g1 = (const float*)d_in[7];
    const float* b1 = (const float*)d_in[8];
    const float* g2 = (const float*)d_in[9];
    const float* b2 = (const float*)d_in[10];
    float* out = (float*)d_out;

    const int fps_smem = 512 + 3 * NPTS * 4 + NPTS * 2;   // wk + coords + perm16
    cudaFuncSetAttribute(k_fps, cudaFuncAttributeMaxDynamicSharedMemorySize, fps_smem);
    const int c1_smem = (64 * 64 + 64 * 64 + 2 * 64) * 4;
    const int c2_smem = (64 * 64 + 64 * 128 + 2 * 128) * 4;
    cudaFuncSetAttribute(k_conv<1>, cudaFuncAttributeMaxDynamicSharedMemorySize, c1_smem);
    cudaFuncSetAttribute(k_conv<2>, cudaFuncAttributeMaxDynamicSharedMemorySize, c2_smem);

    k_zero<<<1, 384>>>();
    k_prep<<<(NB * NPTS) / 256, 256>>>(xyz, pts);
    k_bin<<<NB, 1024>>>(xyz);
    k_fps<<<NB, 1024, fps_smem>>>(xyz, out);
    k_knn<<<(NB * NSP) / 8, 256>>>(xyz);
    k_conv0<<<NSAMP / 64, 128>>>(xyz, w0);
    k_stats<<<1, 128>>>(0, 64, g0, b0);
    k_conv<1><<<NSAMP / 64, 128, c1_smem>>>(w1);
    k_stats<<<1, 128>>>(1, 64, g1, b1);
    k_conv<2><<<NSAMP / 64, 256, c2_smem>>>(w2);
    k_stats<<<1, 128>>>(2, 128, g2, b2);
    k_final<<<(NB * NSP) / 8, 256>>>(out);
}

// round 16
// speedup vs baseline: 1.2790x; 1.2790x over previous
#include <cuda_runtime.h>

typedef unsigned long long ull;
typedef unsigned int uint;

#define NB 4
#define NPTS 8192
#define ND 64
#define NSP 2048
#define NK 16
#define NSAMP (NB*NSP*NK)          // 131072
#define LEAKY 0.1f
#define FULLM 0xffffffffu

#define OUT_XYZ_OFF 0
#define OUT_FEAT_OFF (NB*3*NSP)                 // 24576
#define OUT_FPS_OFF (OUT_FEAT_OFF + NB*128*NSP) // 1073152

// ---------------- scratch (static __device__, allocation-free) ----------------
__device__ float g_pts_t[(size_t)NB*NPTS*ND];   // [b][n][d]   8.4 MB
__device__ float g_sdst[NB*NPTS];               // |p|^2 per point
__device__ float g_newxyz[NB*NSP*3];            // centroids [bs][3]
__device__ int   g_knn[NB*NSP*NK];              // neighbor indices
__device__ float g_y0[(size_t)64*NSAMP];        // channel-major [c][sample]
__device__ float g_y1[(size_t)64*NSAMP];
__device__ float g_y2[(size_t)128*NSAMP];
__device__ double g_sum[3*128];
__device__ double g_sq[3*128];
__device__ float g_scale[3*128];
__device__ float g_bias[3*128];

// ---------------- packed f32x2 helpers (sm_103a; add/mul/fma only!) ----------
__device__ __forceinline__ ull addx2(ull a, ull b) {
    ull r; asm("add.rn.f32x2 %0, %1, %2;" : "=l"(r) : "l"(a), "l"(b)); return r;
}
__device__ __forceinline__ ull mulx2(ull a, ull b) {
    ull r; asm("mul.rn.f32x2 %0, %1, %2;" : "=l"(r) : "l"(a), "l"(b)); return r;
}
__device__ __forceinline__ ull packx2(float lo, float hi) {
    ull r; asm("mov.b64 %0, {%1, %2};" : "=l"(r) : "f"(lo), "f"(hi)); return r;
}
__device__ __forceinline__ void unpackx2(float& lo, float& hi, ull v) {
    asm("mov.b64 {%0, %1}, %2;" : "=f"(lo), "=f"(hi) : "l"(v));
}

// ---------------- zero the BN accumulators (ALL 384 of each!) ----------------
__global__ void k_zero() {
    int i = threadIdx.x;
    if (i < 384) { g_sum[i] = 0.0; g_sq[i] = 0.0; }
}

// ---------------- transpose points + precompute |p|^2 ----------------
__global__ void k_prep(const float* __restrict__ xyz, const float* __restrict__ pts) {
    int idx = blockIdx.x * blockDim.x + threadIdx.x;   // NB*NPTS
    int b = idx >> 13;
    int n = idx & (NPTS - 1);
    const float* xb = xyz + (size_t)b * 3 * NPTS;
    float x = xb[n], y = xb[NPTS + n], z = xb[2 * NPTS + n];
    g_sdst[idx] = __fadd_rn(__fadd_rn(__fmul_rn(x, x), __fmul_rn(y, y)), __fmul_rn(z, z));
    const float* pb = pts + (size_t)b * ND * NPTS;
    float4* dst = (float4*)(g_pts_t + (size_t)idx * ND);
#pragma unroll
    for (int dg = 0; dg < ND / 4; ++dg) {
        float4 v;
        v.x = pb[(dg * 4 + 0) * NPTS + n];
        v.y = pb[(dg * 4 + 1) * NPTS + n];
        v.z = pb[(dg * 4 + 2) * NPTS + n];
        v.w = pb[(dg * 4 + 3) * NPTS + n];
        dst[dg] = v;
    }
}

// ---------------- furthest point sampling: 1 CTA per batch (R10 variant) ------
// Matches jax scan exactly: seed idx 0, dist=min(dist,|p-c|^2) with the
// reference's (dx*dx+dy*dy)+dz*dz rounding order, next=argmax (first max on
// ties). f32x2 packed distance math, scalar min/max bookkeeping with two
// parallel max accumulators (fmax associative over non-NaN: same result).
// Index recovery deferred behind the (rare) block-max ownership test.
__global__ void __launch_bounds__(1024, 1) k_fps(const float* __restrict__ xyz,
                                                 float* __restrict__ out) {
    extern __shared__ char fsm[];
    float* sx = (float*)fsm;
    float* sy = sx + NPTS;
    float* sz = sy + NPTS;
    uint* sval = (uint*)(sz + NPTS);
    uint* sidx = sval + 32;

    const int b = blockIdx.x;
    const int tid = threadIdx.x;
    const int lane = tid & 31;
    const int warp = tid >> 5;
    const float* xb = xyz + (size_t)b * 3 * NPTS;

    ull px2[4], py2[4], pz2[4];
    float dist[8];
    {
        float px[8], py[8], pz[8];
#pragma unroll
        for (int j = 0; j < 8; ++j) {
            int n = j * 1024 + tid;
            px[j] = xb[n];
            py[j] = xb[NPTS + n];
            pz[j] = xb[2 * NPTS + n];
            sx[n] = px[j]; sy[n] = py[j]; sz[n] = pz[j];
            dist[j] = 1e10f;
        }
#pragma unroll
        for (int k = 0; k < 4; ++k) {
            px2[k] = packx2(px[2 * k], px[2 * k + 1]);
            py2[k] = packx2(py[2 * k], py[2 * k + 1]);
            pz2[k] = packx2(pz[2 * k], pz[2 * k + 1]);
        }
    }
    __syncthreads();

    int cur = 0;
    for (int t = 0; t < NSP; ++t) {
        float cx = sx[cur], cy = sy[cur], cz = sz[cur];
        if (tid == 0) {
            out[OUT_FPS_OFF + b * NSP + t] = (float)cur;
            g_newxyz[(b * NSP + t) * 3 + 0] = cx;
            g_newxyz[(b * NSP + t) * 3 + 1] = cy;
            g_newxyz[(b * NSP + t) * 3 + 2] = cz;
            out[OUT_XYZ_OFF + b * 3 * NSP + 0 * NSP + t] = cx;
            out[OUT_XYZ_OFF + b * 3 * NSP + 1 * NSP + t] = cy;
            out[OUT_XYZ_OFF + b * 3 * NSP + 2 * NSP + t] = cz;
        }
        if (t == NSP - 1) break;

        // p - c  ==  p + (-c)  (negation exact in IEEE)
        const ull ncx2 = packx2(-cx, -cx);
        const ull ncy2 = packx2(-cy, -cy);
        const ull ncz2 = packx2(-cz, -cz);

        float bestA = -1.0f, bestB = -1.0f;   // two parallel chains
#pragma unroll
        for (int k = 0; k < 4; ++k) {
            ull dx2 = addx2(px2[k], ncx2);
            ull dy2 = addx2(py2[k], ncy2);
            ull dz2 = addx2(pz2[k], ncz2);
            ull m0 = mulx2(dx2, dx2);
            ull m1 = mulx2(dy2, dy2);
            ull m2 = mulx2(dz2, dz2);
            ull s = addx2(addx2(m0, m1), m2);   // same rounding order as reference
            float dlo, dhi;
            unpackx2(dlo, dhi, s);
            float a = fminf(dist[2 * k], dlo);
            dist[2 * k] = a;
            float c2 = fminf(dist[2 * k + 1], dhi);
            dist[2 * k + 1] = c2;
            if (k & 1) bestB = fmaxf(bestB, fmaxf(a, c2));
            else       bestA = fmaxf(bestA, fmaxf(a, c2));
        }
        float best = fmaxf(bestA, bestB);

        // stage 1: warp max of dist bits (dist >= 0 so bits are order-monotone)
        uint bb = __float_as_uint(best);
        uint wmax = __reduce_max_sync(FULLM, bb);
        if (lane == 0) sval[warp] = wmax;
        __syncthreads();

        // stage 2: ALL warps redundantly reduce the 32 partials
        uint g = __reduce_max_sync(FULLM, sval[lane]);

        // index recovery only on lanes owning the block max (~1/1024 threads)
        uint comp = 0u;
        if (bb == g) {
            float gb = __uint_as_float(g);      // exact: fmin/fmax return inputs
#pragma unroll
            for (int j = 7; j >= 0; --j)
                if (dist[j] == gb) comp = FULLM - (uint)(j * 1024 + tid);
        }
        uint wc = __reduce_max_sync(FULLM, comp);
        if (lane == 0) sidx[warp] = wc;
        __syncthreads();

        uint r = __reduce_max_sync(FULLM, sidx[lane]);
        cur = (int)(FULLM - r);
    }
}

// ---------------- kNN: one warp per (b,s), warp-shared sorted top-16 ----------
// (R7 variant, measured 107-113us)
__device__ __forceinline__ uint sortable(float v) {
    uint u = __float_as_uint(v);
    return (u & 0x80000000u) ? ~u : (u | 0x80000000u);
}

__global__ void __launch_bounds__(256) k_knn(const float* __restrict__ xyz) {
    const int lane = threadIdx.x & 31;
    const int w = threadIdx.x >> 5;
    const int gw = blockIdx.x * 8 + w;   // 0 .. NB*NSP-1
    const int b = gw >> 11;
    const int bs = gw;

    float cx = g_newxyz[bs * 3 + 0];
    float cy = g_newxyz[bs * 3 + 1];
    float cz = g_newxyz[bs * 3 + 2];
    float ssrc = __fadd_rn(__fadd_rn(__fmul_rn(cx, cx), __fmul_rn(cy, cy)),
                           __fmul_rn(cz, cz));

    const float* xb = xyz + (size_t)b * 3 * NPTS;
    const float4* x4 = (const float4*)xb;
    const float4* y4 = (const float4*)(xb + NPTS);
    const float4* z4 = (const float4*)(xb + 2 * NPTS);
    const float4* s4 = (const float4*)(g_sdst + b * NPTS);

    ull L = ~0ull;                 // lanes 0..15: sorted ascending top-16
    uint tauhi = 0xFFFFFFFFu;      // hi32 of L[15]

    for (int gidx = lane; gidx < NPTS / 4; gidx += 32) {   // 64 uniform steps
        float4 X = x4[gidx], Y = y4[gidx], Z = z4[gidx], S = s4[gidx];
        const float pxa[4] = {X.x, X.y, X.z, X.w};
        const float pya[4] = {Y.x, Y.y, Y.z, Y.w};
        const float pza[4] = {Z.x, Z.y, Z.z, Z.w};
        const float sda[4] = {S.x, S.y, S.z, S.w};
        uint sa[4];
#pragma unroll
        for (int q = 0; q < 4; ++q) {
            float dot = fmaf(cz, pza[q], fmaf(cy, pya[q], cx * pxa[q]));
            float v = fmaf(-2.0f, dot, ssrc);    // exact: -2*dot has no rounding
            v = __fadd_rn(v, sda[q]);
            sa[q] = sortable(v);
        }
#pragma unroll
        for (int q = 0; q < 4; ++q) {
            uint pass = __ballot_sync(FULLM, sa[q] <= tauhi);
            while (pass) {
                const int src = __ffs(pass) - 1;
                pass &= pass - 1;
                uint shi = __shfl_sync(FULLM, sa[q], src);
                uint sgi = (uint)__shfl_sync(FULLM, gidx, src);
                ull key = ((ull)shi << 32) | (sgi * 4 + q);
                ull l15 = __shfl_sync(FULLM, L, 15);
                if (key < l15) {                 // exact recheck (ties by index)
                    ull v = (lane < 16) ? L : ~0ull;
                    uint pos = __popc(__ballot_sync(FULLM, v < key));
                    ull vup = __shfl_up_sync(FULLM, L, 1);
                    ull nv = (lane < (int)pos) ? L : ((lane == (int)pos) ? key : vup);
                    if (lane < 16) L = nv;
                    tauhi = (uint)(__shfl_sync(FULLM, L, 15) >> 32);
                }
            }
        }
    }
    if (lane < NK) g_knn[bs * NK + lane] = (int)(L & 0xFFFFFFFFu);
}

// ---------------- conv0: gather(67ch) -> 64ch GEMM + BN partials ----------------
__global__ void __launch_bounds__(128) k_conv0(const float* __restrict__ xyz,
                                               const float* __restrict__ w0) {
    __shared__ float Xs[67 * 64];
    __shared__ float Ws[67 * 64];
    __shared__ int   n_sh[64];
    __shared__ float ps[64], pq[64];

    const int tid = threadIdx.x;
    const int s0 = blockIdx.x * 64;          // first sample of this block
    const int b = blockIdx.x >> 9;           // 512 blocks per batch (uniform)
    const float* xb = xyz + (size_t)b * 3 * NPTS;

    if (tid < 64) { ps[tid] = 0.0f; pq[tid] = 0.0f; }

    for (int i = tid; i < 64 * 67; i += 128) {
        int o = i / 67, c = i - o * 67;
        Ws[c * 64 + o] = w0[i];
    }
    if (tid < 64) {
        int samp = s0 + tid;
        int bs = samp >> 4, k = samp & 15;
        int n = g_knn[bs * NK + k];
        n_sh[tid] = n;
        float cx = g_newxyz[bs * 3 + 0];
        float cy = g_newxyz[bs * 3 + 1];
        float cz = g_newxyz[bs * 3 + 2];
        Xs[0 * 64 + tid] = xb[n] - cx;
        Xs[1 * 64 + tid] = xb[NPTS + n] - cy;
        Xs[2 * 64 + tid] = xb[2 * NPTS + n] - cz;
    }
    __syncthreads();
    for (int ci = tid; ci < 64 * 16; ci += 128) {
        int m = ci & 63, dg = ci >> 6;
        int n = n_sh[m];
        float4 v = *(const float4*)(g_pts_t + ((size_t)(b * NPTS + n) * ND + dg * 4));
        Xs[(3 + dg * 4 + 0) * 64 + m] = v.x;
        Xs[(3 + dg * 4 + 1) * 64 + m] = v.y;
        Xs[(3 + dg * 4 + 2) * 64 + m] = v.z;
        Xs[(3 + dg * 4 + 3) * 64 + m] = v.w;
    }
    __syncthreads();

    const int sg = tid & 15;     // 4 samples
    const int og = tid >> 4;     // 8 outputs
    float acc[4][8];
#pragma unroll
    for (int i = 0; i < 4; ++i)
#pragma unroll
        for (int j = 0; j < 8; ++j) acc[i][j] = 0.0f;

    const float4* Xs4 = (const float4*)Xs;
    const float4* Ws4 = (const float4*)Ws;
#pragma unroll 4
    for (int c = 0; c < 67; ++c) {
        float4 xv = Xs4[c * 16 + sg];
        float4 wa = Ws4[c * 16 + og * 2];
        float4 wb = Ws4[c * 16 + og * 2 + 1];
        float xs[4] = {xv.x, xv.y, xv.z, xv.w};
        float ws[8] = {wa.x, wa.y, wa.z, wa.w, wb.x, wb.y, wb.z, wb.w};
#pragma unroll
        for (int i = 0; i < 4; ++i)
#pragma unroll
            for (int j = 0; j < 8; ++j) acc[i][j] = fmaf(xs[i], ws[j], acc[i][j]);
    }
#pragma unroll
    for (int j = 0; j < 8; ++j) {
        float4 v = make_float4(acc[0][j], acc[1][j], acc[2][j], acc[3][j]);
        *(float4*)&g_y0[(size_t)(og * 8 + j) * NSAMP + s0 + sg * 4] = v;
        float su = acc[0][j] + acc[1][j] + acc[2][j] + acc[3][j];
        float qu = acc[0][j] * acc[0][j] + acc[1][j] * acc[1][j] +
                   acc[2][j] * acc[2][j] + acc[3][j] * acc[3][j];
        atomicAdd(&ps[og * 8 + j], su);
        atomicAdd(&pq[og * 8 + j], qu);
    }
    __syncthreads();
    if (tid < 64) {
        atomicAdd(&g_sum[0 * 128 + tid], (double)ps[tid]);
        atomicAdd(&g_sq[0 * 128 + tid], (double)pq[tid]);
    }
}

// ---------------- BN stats -> fused scale/bias ----------------
__global__ void k_stats(int st, int cout, const float* __restrict__ gamma,
                        const float* __restrict__ beta) {
    int c = threadIdx.x;
    if (c < cout) {
        double n = (double)NSAMP;
        double mean = g_sum[st * 128 + c] / n;
        double var = g_sq[st * 128 + c] / n - mean * mean;
        double rstd = 1.0 / sqrt(var + 1e-5);
        double sc = (double)gamma[c] * rstd;
        g_scale[st * 128 + c] = (float)sc;
        g_bias[st * 128 + c] = (float)((double)beta[c] - mean * sc);
    }
}

// ---------------- conv1 / conv2: act(BN prev) -> GEMM + BN partials ----------------
template <int LAYER>
__global__ void __launch_bounds__((LAYER == 1) ? 128 : 256)
k_conv(const float* __restrict__ w) {
    constexpr int COUT = (LAYER == 1) ? 64 : 128;
    constexpr int ST_IN = LAYER - 1;
    constexpr int ST_OUT = LAYER;
    const float* yin = (LAYER == 1) ? g_y0 : g_y1;
    float* yout = (LAYER == 1) ? g_y1 : g_y2;

    extern __shared__ float shm[];
    float* Xs = shm;                 // 64*64
    float* Ws = Xs + 64 * 64;        // 64*COUT
    float* ps = Ws + 64 * COUT;
    float* pq = ps + COUT;

    const int tid = threadIdx.x;
    constexpr int NTHR = (COUT / 8) * 16;
    const int s0 = blockIdx.x * 64;

    for (int c = tid; c < COUT; c += NTHR) { ps[c] = 0.0f; pq[c] = 0.0f; }
    for (int i = tid; i < 64 * COUT; i += NTHR) {
        int o = i >> 6, c = i & 63;
        Ws[c * COUT + o] = w[i];
    }
    const float* sc = g_scale + ST_IN * 128;
    const float* bi = g_bias + ST_IN * 128;
    for (int i = tid; i < 64 * 64; i += NTHR) {
        int m = i & 63, c = i >> 6;
        float v = yin[(size_t)c * NSAMP + s0 + m];
        v = fmaf(v, sc[c], bi[c]);
        v = (v > 0.0f) ? v : LEAKY * v;
        Xs[c * 64 + m] = v;
    }
    __syncthreads();

    const int sg = tid & 15;
    const int og = tid >> 4;
    float acc[4][8];
#pragma unroll
    for (int i = 0; i < 4; ++i)
#pragma unroll
        for (int j = 0; j < 8; ++j) acc[i][j] = 0.0f;

    const float4* Xs4 = (const float4*)Xs;
    const float4* Ws4 = (const float4*)Ws;
#pragma unroll 4
    for (int c = 0; c < 64; ++c) {
        float4 xv = Xs4[c * 16 + sg];
        float4 wa = Ws4[c * (COUT / 4) + og * 2];
        float4 wb = Ws4[c * (COUT / 4) + og * 2 + 1];
        float xs[4] = {xv.x, xv.y, xv.z, xv.w};
        float ws[8] = {wa.x, wa.y, wa.z, wa.w, wb.x, wb.y, wb.z, wb.w};
#pragma unroll
        for (int i = 0; i < 4; ++i)
#pragma unroll
            for (int j = 0; j < 8; ++j) acc[i][j] = fmaf(xs[i], ws[j], acc[i][j]);
    }
#pragma unroll
    for (int j = 0; j < 8; ++j) {
        float4 v = make_float4(acc[0][j], acc[1][j], acc[2][j], acc[3][j]);
        *(float4*)&yout[(size_t)(og * 8 + j) * NSAMP + s0 + sg * 4] = v;
        float su = acc[0][j] + acc[1][j] + acc[2][j] + acc[3][j];
        float qu = acc[0][j] * acc[0][j] + acc[1][j] * acc[1][j] +
                   acc[2][j] * acc[2][j] + acc[3][j] * acc[3][j];
        atomicAdd(&ps[og * 8 + j], su);
        atomicAdd(&pq[og * 8 + j], qu);
    }
    __syncthreads();
    for (int c = tid; c < COUT; c += NTHR) {
        atomicAdd(&g_sum[ST_OUT * 128 + c], (double)ps[c]);
        atomicAdd(&g_sq[ST_OUT * 128 + c], (double)pq[c]);
    }
}

// ---------------- final: act(BN2) + max over K ----------------
__global__ void __launch_bounds__(256) k_final(float* __restrict__ out) {
    const int lane = threadIdx.x & 31;
    const int gw = (blockIdx.x * blockDim.x + threadIdx.x) >> 5;  // bs index
    const int b = gw >> 11;
    const int s = gw & 2047;
    const float* sc = g_scale + 2 * 128;
    const float* bi = g_bias + 2 * 128;
#pragma unroll
    for (int j = 0; j < 4; ++j) {
        int o = lane + 32 * j;
        const float4* row = (const float4*)(g_y2 + (size_t)o * NSAMP + gw * NK);
        float scv = sc[o], biv = bi[o];
        float m = -3.4e38f;
#pragma unroll
        for (int q = 0; q < 4; ++q) {
            float4 v4 = row[q];
            float vv[4] = {v4.x, v4.y, v4.z, v4.w};
#pragma unroll
            for (int r = 0; r < 4; ++r) {
                float v = fmaf(vv[r], scv, biv);
                v = (v > 0.0f) ? v : LEAKY * v;
                m = fmaxf(m, v);
            }
        }
        out[OUT_FEAT_OFF + ((size_t)b * 128 + o) * NSP + s] = m;
    }
}

// ---------------- launch ----------------
extern "C" void kernel_launch(void* const* d_in, const int* in_sizes, int n_in,
                              void* d_out, int out_size) {
    (void)in_sizes; (void)n_in; (void)out_size;
    const float* xyz = (const float*)d_in[0];
    const float* pts = (const float*)d_in[1];
    const float* w0 = (const float*)d_in[2];
    const float* w1 = (const float*)d_in[3];
    const float* w2 = (const float*)d_in[4];
    const float* g0 = (const float*)d_in[5];
    const float* b0 = (const float*)d_in[6];
    const float* g1 = (const float*)d_in[7];
    const float* b1 = (const float*)d_in[8];
    const float* g2 = (const float*)d_in[9];
    const float* b2 = (const float*)d_in[10];
    float* out = (float*)d_out;

    const int fps_smem = 3 * NPTS * 4 + 64 * 4 + 16;
    cudaFuncSetAttribute(k_fps, cudaFuncAttributeMaxDynamicSharedMemorySize, fps_smem);
    const int c1_smem = (64 * 64 + 64 * 64 + 2 * 64) * 4;
    const int c2_smem = (64 * 64 + 64 * 128 + 2 * 128) * 4;
    cudaFuncSetAttribute(k_conv<1>, cudaFuncAttributeMaxDynamicSharedMemorySize, c1_smem);
    cudaFuncSetAttribute(k_conv<2>, cudaFuncAttributeMaxDynamicSharedMemorySize, c2_smem);

    k_zero<<<1, 384>>>();
    k_prep<<<(NB * NPTS) / 256, 256>>>(xyz, pts);
    k_fps<<<NB, 1024, fps_smem>>>(xyz, out);
    k_knn<<<(NB * NSP) / 8, 256>>>(xyz);
    k_conv0<<<NSAMP / 64, 128>>>(xyz, w0);
    k_stats<<<1, 128>>>(0, 64, g0, b0);
    k_conv<1><<<NSAMP / 64, 128, c1_smem>>>(w1);
    k_stats<<<1, 128>>>(1, 64, g1, b1);
    k_conv<2><<<NSAMP / 64, 256, c2_smem>>>(w2);
    k_stats<<<1, 128>>>(2, 128, g2, b2);
    k_final<<<(NB * NSP) / 8, 256>>>(out);
}

// round 17
// speedup vs baseline: 1.3121x; 1.0258x over previous
#include <cuda_runtime.h>

typedef unsigned long long ull;
typedef unsigned int uint;

#define NB 4
#define NPTS 8192
#define ND 64
#define NSP 2048
#define NK 16
#define NSAMP (NB*NSP*NK)          // 131072
#define LEAKY 0.1f
#define FULLM 0xffffffffu

#define OUT_XYZ_OFF 0
#define OUT_FEAT_OFF (NB*3*NSP)                 // 24576
#define OUT_FPS_OFF (OUT_FEAT_OFF + NB*128*NSP) // 1073152

// ---------------- scratch (static __device__, allocation-free) ----------------
__device__ float g_pts_t[(size_t)NB*NPTS*ND];   // [b][n][d]   8.4 MB
__device__ float g_sdst[NB*NPTS];               // |p|^2 per point
__device__ float g_newxyz[NB*NSP*3];            // centroids [bs][3]
__device__ int   g_knn[NB*NSP*NK];              // neighbor indices
__device__ float g_y0[(size_t)64*NSAMP];        // channel-major [c][sample]
__device__ float g_y1[(size_t)64*NSAMP];
__device__ float g_y2[(size_t)128*NSAMP];
__device__ double g_sum[3*128];
__device__ double g_sq[3*128];
__device__ float g_scale[3*128];
__device__ float g_bias[3*128];

// ---------------- packed f32x2 helpers (sm_103a; add/mul/fma only) -----------
__device__ __forceinline__ ull addx2(ull a, ull b) {
    ull r; asm("add.rn.f32x2 %0, %1, %2;" : "=l"(r) : "l"(a), "l"(b)); return r;
}
__device__ __forceinline__ ull mulx2(ull a, ull b) {
    ull r; asm("mul.rn.f32x2 %0, %1, %2;" : "=l"(r) : "l"(a), "l"(b)); return r;
}
__device__ __forceinline__ ull fmax2(ull a, ull b, ull c) {
    ull r; asm("fma.rn.f32x2 %0, %1, %2, %3;" : "=l"(r) : "l"(a), "l"(b), "l"(c));
    return r;
}
__device__ __forceinline__ ull packx2(float lo, float hi) {
    ull r; asm("mov.b64 %0, {%1, %2};" : "=l"(r) : "f"(lo), "f"(hi)); return r;
}
__device__ __forceinline__ void unpackx2(float& lo, float& hi, ull v) {
    asm("mov.b64 {%0, %1}, %2;" : "=f"(lo), "=f"(hi) : "l"(v));
}

// ---------------- zero the BN accumulators (ALL 384 of each!) ----------------
__global__ void k_zero() {
    int i = threadIdx.x;
    if (i < 384) { g_sum[i] = 0.0; g_sq[i] = 0.0; }
}

// ---------------- transpose points + precompute |p|^2 ----------------
__global__ void k_prep(const float* __restrict__ xyz, const float* __restrict__ pts) {
    int idx = blockIdx.x * blockDim.x + threadIdx.x;   // NB*NPTS
    int b = idx >> 13;
    int n = idx & (NPTS - 1);
    const float* xb = xyz + (size_t)b * 3 * NPTS;
    float x = xb[n], y = xb[NPTS + n], z = xb[2 * NPTS + n];
    g_sdst[idx] = __fadd_rn(__fadd_rn(__fmul_rn(x, x), __fmul_rn(y, y)), __fmul_rn(z, z));
    const float* pb = pts + (size_t)b * ND * NPTS;
    float4* dst = (float4*)(g_pts_t + (size_t)idx * ND);
#pragma unroll
    for (int dg = 0; dg < ND / 4; ++dg) {
        float4 v;
        v.x = pb[(dg * 4 + 0) * NPTS + n];
        v.y = pb[(dg * 4 + 1) * NPTS + n];
        v.z = pb[(dg * 4 + 2) * NPTS + n];
        v.w = pb[(dg * 4 + 3) * NPTS + n];
        dst[dg] = v;
    }
}

// ---------------- furthest point sampling: 1 CTA per batch (exact R10) -------
__global__ void __launch_bounds__(1024, 1) k_fps(const float* __restrict__ xyz,
                                                 float* __restrict__ out) {
    extern __shared__ char fsm[];
    float* sx = (float*)fsm;
    float* sy = sx + NPTS;
    float* sz = sy + NPTS;
    uint* sval = (uint*)(sz + NPTS);
    uint* sidx = sval + 32;

    const int b = blockIdx.x;
    const int tid = threadIdx.x;
    const int lane = tid & 31;
    const int warp = tid >> 5;
    const float* xb = xyz + (size_t)b * 3 * NPTS;

    ull px2[4], py2[4], pz2[4];
    float dist[8];
    {
        float px[8], py[8], pz[8];
#pragma unroll
        for (int j = 0; j < 8; ++j) {
            int n = j * 1024 + tid;
            px[j] = xb[n];
            py[j] = xb[NPTS + n];
            pz[j] = xb[2 * NPTS + n];
            sx[n] = px[j]; sy[n] = py[j]; sz[n] = pz[j];
            dist[j] = 1e10f;
        }
#pragma unroll
        for (int k = 0; k < 4; ++k) {
            px2[k] = packx2(px[2 * k], px[2 * k + 1]);
            py2[k] = packx2(py[2 * k], py[2 * k + 1]);
            pz2[k] = packx2(pz[2 * k], pz[2 * k + 1]);
        }
    }
    __syncthreads();

    int cur = 0;
    for (int t = 0; t < NSP; ++t) {
        float cx = sx[cur], cy = sy[cur], cz = sz[cur];
        if (tid == 0) {
            out[OUT_FPS_OFF + b * NSP + t] = (float)cur;
            g_newxyz[(b * NSP + t) * 3 + 0] = cx;
            g_newxyz[(b * NSP + t) * 3 + 1] = cy;
            g_newxyz[(b * NSP + t) * 3 + 2] = cz;
            out[OUT_XYZ_OFF + b * 3 * NSP + 0 * NSP + t] = cx;
            out[OUT_XYZ_OFF + b * 3 * NSP + 1 * NSP + t] = cy;
            out[OUT_XYZ_OFF + b * 3 * NSP + 2 * NSP + t] = cz;
        }
        if (t == NSP - 1) break;

        // p - c  ==  p + (-c)  (negation exact in IEEE)
        const ull ncx2 = packx2(-cx, -cx);
        const ull ncy2 = packx2(-cy, -cy);
        const ull ncz2 = packx2(-cz, -cz);

        float best = -1.0f;
#pragma unroll
        for (int k = 0; k < 4; ++k) {
            ull dx2 = addx2(px2[k], ncx2);
            ull dy2 = addx2(py2[k], ncy2);
            ull dz2 = addx2(pz2[k], ncz2);
            ull m0 = mulx2(dx2, dx2);
            ull m1 = mulx2(dy2, dy2);
            ull m2 = mulx2(dz2, dz2);
            ull s = addx2(addx2(m0, m1), m2);   // same order as reference
            float dlo, dhi;
            unpackx2(dlo, dhi, s);
            float a = fminf(dist[2 * k], dlo);
            dist[2 * k] = a;
            best = fmaxf(best, a);
            float c2 = fminf(dist[2 * k + 1], dhi);
            dist[2 * k + 1] = c2;
            best = fmaxf(best, c2);
        }

        // stage 1: warp max of dist bits (dist >= 0 so bits are order-monotone)
        uint bb = __float_as_uint(best);
        uint wmax = __reduce_max_sync(FULLM, bb);
        if (lane == 0) sval[warp] = wmax;
        __syncthreads();

        // stage 2: ALL warps redundantly reduce the 32 partials
        uint g = __reduce_max_sync(FULLM, sval[lane]);

        // index recovery only on lanes owning the block max (~1/1024 threads)
        uint comp = 0u;
        if (bb == g) {
            float gb = __uint_as_float(g);
#pragma unroll
            for (int j = 7; j >= 0; --j)
                if (dist[j] == gb) comp = FULLM - (uint)(j * 1024 + tid);
        }
        uint wc = __reduce_max_sync(FULLM, comp);
        if (lane == 0) sidx[warp] = wc;
        __syncthreads();

        uint r = __reduce_max_sync(FULLM, sidx[lane]);
        cur = (int)(FULLM - r);
    }
}

// ---------------- kNN: one warp per (b,s), warp-shared sorted top-16 ----------
__device__ __forceinline__ uint sortable(float v) {
    uint u = __float_as_uint(v);
    return (u & 0x80000000u) ? ~u : (u | 0x80000000u);
}

__global__ void __launch_bounds__(256) k_knn(const float* __restrict__ xyz) {
    const int lane = threadIdx.x & 31;
    const int w = threadIdx.x >> 5;
    const int gw = blockIdx.x * 8 + w;   // 0 .. NB*NSP-1
    const int b = gw >> 11;
    const int bs = gw;

    float cx = g_newxyz[bs * 3 + 0];
    float cy = g_newxyz[bs * 3 + 1];
    float cz = g_newxyz[bs * 3 + 2];
    float ssrc = __fadd_rn(__fadd_rn(__fmul_rn(cx, cx), __fmul_rn(cy, cy)),
                           __fmul_rn(cz, cz));

    const float* xb = xyz + (size_t)b * 3 * NPTS;
    const float4* x4 = (const float4*)xb;
    const float4* y4 = (const float4*)(xb + NPTS);
    const float4* z4 = (const float4*)(xb + 2 * NPTS);
    const float4* s4 = (const float4*)(g_sdst + b * NPTS);

    ull L = ~0ull;                 // lanes 0..15: sorted ascending top-16
    uint tauhi = 0xFFFFFFFFu;      // hi32 of L[15]

    for (int gidx = lane; gidx < NPTS / 4; gidx += 32) {   // 64 uniform steps
        float4 X = x4[gidx], Y = y4[gidx], Z = z4[gidx], S = s4[gidx];
        const float pxa[4] = {X.x, X.y, X.z, X.w};
        const float pya[4] = {Y.x, Y.y, Y.z, Y.w};
        const float pza[4] = {Z.x, Z.y, Z.z, Z.w};
        const float sda[4] = {S.x, S.y, S.z, S.w};
        uint sa[4];
#pragma unroll
        for (int q = 0; q < 4; ++q) {
            float dot = fmaf(cz, pza[q], fmaf(cy, pya[q], cx * pxa[q]));
            float v = fmaf(-2.0f, dot, ssrc);    // exact: -2*dot has no rounding
            v = __fadd_rn(v, sda[q]);
            sa[q] = sortable(v);
        }
#pragma unroll
        for (int q = 0; q < 4; ++q) {
            uint pass = __ballot_sync(FULLM, sa[q] <= tauhi);
            while (pass) {
                const int src = __ffs(pass) - 1;
                pass &= pass - 1;
                uint shi = __shfl_sync(FULLM, sa[q], src);
                uint sgi = (uint)__shfl_sync(FULLM, gidx, src);
                ull key = ((ull)shi << 32) | (sgi * 4 + q);
                ull l15 = __shfl_sync(FULLM, L, 15);
                if (key < l15) {                 // exact recheck (ties by index)
                    ull v = (lane < 16) ? L : ~0ull;
                    uint pos = __popc(__ballot_sync(FULLM, v < key));
                    ull vup = __shfl_up_sync(FULLM, L, 1);
                    ull nv = (lane < (int)pos) ? L : ((lane == (int)pos) ? key : vup);
                    if (lane < 16) L = nv;
                    tauhi = (uint)(__shfl_sync(FULLM, L, 15) >> 32);
                }
            }
        }
    }
    if (lane < NK) g_knn[bs * NK + lane] = (int)(L & 0xFFFFFFFFu);
}

// ---------------- conv0: gather(67ch) -> 64ch GEMM (FFMA2) + BN partials ------
__global__ void __launch_bounds__(128) k_conv0(const float* __restrict__ xyz,
                                               const float* __restrict__ w0) {
    __shared__ float Xs[67 * 64];
    __shared__ float Ws[67 * 64];
    __shared__ int   n_sh[64];
    __shared__ float ps[64], pq[64];

    const int tid = threadIdx.x;
    const int s0 = blockIdx.x * 64;          // first sample of this block
    const int b = blockIdx.x >> 9;           // 512 blocks per batch (uniform)
    const float* xb = xyz + (size_t)b * 3 * NPTS;

    if (tid < 64) { ps[tid] = 0.0f; pq[tid] = 0.0f; }

    // stage weights transposed: Ws[c][o] (channels o adjacent -> packed pairs)
    for (int i = tid; i < 64 * 67; i += 128) {
        int o = i / 67, c = i - o * 67;
        Ws[c * 64 + o] = w0[i];
    }
    if (tid < 64) {
        int samp = s0 + tid;
        int bs = samp >> 4, k = samp & 15;
        int n = g_knn[bs * NK + k];
        n_sh[tid] = n;
        float cx = g_newxyz[bs * 3 + 0];
        float cy = g_newxyz[bs * 3 + 1];
        float cz = g_newxyz[bs * 3 + 2];
        Xs[0 * 64 + tid] = xb[n] - cx;
        Xs[1 * 64 + tid] = xb[NPTS + n] - cy;
        Xs[2 * 64 + tid] = xb[2 * NPTS + n] - cz;
    }
    __syncthreads();
    for (int ci = tid; ci < 64 * 16; ci += 128) {
        int m = ci & 63, dg = ci >> 6;
        int n = n_sh[m];
        float4 v = *(const float4*)(g_pts_t + ((size_t)(b * NPTS + n) * ND + dg * 4));
        Xs[(3 + dg * 4 + 0) * 64 + m] = v.x;
        Xs[(3 + dg * 4 + 1) * 64 + m] = v.y;
        Xs[(3 + dg * 4 + 2) * 64 + m] = v.z;
        Xs[(3 + dg * 4 + 3) * 64 + m] = v.w;
    }
    __syncthreads();

    const int sg = tid & 15;     // 4 samples
    const int og = tid >> 4;     // 8 outputs (4 packed channel-pairs)
    ull acc2[4][4];              // [sample][chpair], each = (ch 2q, ch 2q+1)
#pragma unroll
    for (int i = 0; i < 4; ++i)
#pragma unroll
        for (int q = 0; q < 4; ++q) acc2[i][q] = 0ull;

    const float4* Xs4 = (const float4*)Xs;
#pragma unroll 4
    for (int c = 0; c < 67; ++c) {
        float4 xv = Xs4[c * 16 + sg];
        const ull* wrow = (const ull*)&Ws[c * 64 + og * 8];   // 4 packed pairs
        ull w2[4] = {wrow[0], wrow[1], wrow[2], wrow[3]};
        ull xbr[4] = {packx2(xv.x, xv.x), packx2(xv.y, xv.y),
                      packx2(xv.z, xv.z), packx2(xv.w, xv.w)};
#pragma unroll
        for (int i = 0; i < 4; ++i)
#pragma unroll
            for (int q = 0; q < 4; ++q)
                acc2[i][q] = fmax2(xbr[i], w2[q], acc2[i][q]);   // per-elem == fmaf
    }
    // unpack: acc[i][2q+h]
    float acc[4][8];
#pragma unroll
    for (int i = 0; i < 4; ++i)
#pragma unroll
        for (int q = 0; q < 4; ++q)
            unpackx2(acc[i][2 * q], acc[i][2 * q + 1], acc2[i][q]);
#pragma unroll
    for (int j = 0; j < 8; ++j) {
        float4 v = make_float4(acc[0][j], acc[1][j], acc[2][j], acc[3][j]);
        *(float4*)&g_y0[(size_t)(og * 8 + j) * NSAMP + s0 + sg * 4] = v;
        float su = acc[0][j] + acc[1][j] + acc[2][j] + acc[3][j];
        float qu = acc[0][j] * acc[0][j] + acc[1][j] * acc[1][j] +
                   acc[2][j] * acc[2][j] + acc[3][j] * acc[3][j];
        atomicAdd(&ps[og * 8 + j], su);
        atomicAdd(&pq[og * 8 + j], qu);
    }
    __syncthreads();
    if (tid < 64) {
        atomicAdd(&g_sum[0 * 128 + tid], (double)ps[tid]);
        atomicAdd(&g_sq[0 * 128 + tid], (double)pq[tid]);
    }
}

// ---------------- BN stats -> fused scale/bias ----------------
__global__ void k_stats(int st, int cout, const float* __restrict__ gamma,
                        const float* __restrict__ beta) {
    int c = threadIdx.x;
    if (c < cout) {
        double n = (double)NSAMP;
        double mean = g_sum[st * 128 + c] / n;
        double var = g_sq[st * 128 + c] / n - mean * mean;
        double rstd = 1.0 / sqrt(var + 1e-5);
        double sc = (double)gamma[c] * rstd;
        g_scale[st * 128 + c] = (float)sc;
        g_bias[st * 128 + c] = (float)((double)beta[c] - mean * sc);
    }
}

// ---------------- conv1 / conv2: act(BN prev) -> GEMM (FFMA2) + BN partials ---
template <int LAYER>
__global__ void __launch_bounds__((LAYER == 1) ? 128 : 256)
k_conv(const float* __restrict__ w) {
    constexpr int COUT = (LAYER == 1) ? 64 : 128;
    constexpr int ST_IN = LAYER - 1;
    constexpr int ST_OUT = LAYER;
    const float* yin = (LAYER == 1) ? g_y0 : g_y1;
    float* yout = (LAYER == 1) ? g_y1 : g_y2;

    extern __shared__ float shm[];
    float* Xs = shm;                 // 64*64
    float* Ws = Xs + 64 * 64;        // 64*COUT
    float* ps = Ws + 64 * COUT;
    float* pq = ps + COUT;

    const int tid = threadIdx.x;
    constexpr int NTHR = (COUT / 8) * 16;
    const int s0 = blockIdx.x * 64;

    for (int c = tid; c < COUT; c += NTHR) { ps[c] = 0.0f; pq[c] = 0.0f; }
    for (int i = tid; i < 64 * COUT; i += NTHR) {
        int o = i >> 6, c = i & 63;
        Ws[c * COUT + o] = w[i];
    }
    const float* sc = g_scale + ST_IN * 128;
    const float* bi = g_bias + ST_IN * 128;
    for (int i = tid; i < 64 * 64; i += NTHR) {
        int m = i & 63, c = i >> 6;
        float v = yin[(size_t)c * NSAMP + s0 + m];
        v = fmaf(v, sc[c], bi[c]);
        v = (v > 0.0f) ? v : LEAKY * v;
        Xs[c * 64 + m] = v;
    }
    __syncthreads();

    const int sg = tid & 15;
    const int og = tid >> 4;
    ull acc2[4][4];
#pragma unroll
    for (int i = 0; i < 4; ++i)
#pragma unroll
        for (int q = 0; q < 4; ++q) acc2[i][q] = 0ull;

    const float4* Xs4 = (const float4*)Xs;
#pragma unroll 4
    for (int c = 0; c < 64; ++c) {
        float4 xv = Xs4[c * 16 + sg];
        const ull* wrow = (const ull*)&Ws[c * COUT + og * 8];
        ull w2[4] = {wrow[0], wrow[1], wrow[2], wrow[3]};
        ull xbr[4] = {packx2(xv.x, xv.x), packx2(xv.y, xv.y),
                      packx2(xv.z, xv.z), packx2(xv.w, xv.w)};
#pragma unroll
        for (int i = 0; i < 4; ++i)
#pragma unroll
            for (int q = 0; q < 4; ++q)
                acc2[i][q] = fmax2(xbr[i], w2[q], acc2[i][q]);   // per-elem == fmaf
    }
    float acc[4][8];
#pragma unroll
    for (int i = 0; i < 4; ++i)
#pragma unroll
        for (int q = 0; q < 4; ++q)
            unpackx2(acc[i][2 * q], acc[i][2 * q + 1], acc2[i][q]);
#pragma unroll
    for (int j = 0; j < 8; ++j) {
        float4 v = make_float4(acc[0][j], acc[1][j], acc[2][j], acc[3][j]);
        *(float4*)&yout[(size_t)(og * 8 + j) * NSAMP + s0 + sg * 4] = v;
        float su = acc[0][j] + acc[1][j] + acc[2][j] + acc[3][j];
        float qu = acc[0][j] * acc[0][j] + acc[1][j] * acc[1][j] +
                   acc[2][j] * acc[2][j] + acc[3][j] * acc[3][j];
        atomicAdd(&ps[og * 8 + j], su);
        atomicAdd(&pq[og * 8 + j], qu);
    }
    __syncthreads();
    for (int c = tid; c < COUT; c += NTHR) {
        atomicAdd(&g_sum[ST_OUT * 128 + c], (double)ps[c]);
        atomicAdd(&g_sq[ST_OUT * 128 + c], (double)pq[c]);
    }
}

// ---------------- final: act(BN2) + max over K ----------------
__global__ void __launch_bounds__(256) k_final(float* __restrict__ out) {
    const int lane = threadIdx.x & 31;
    const int gw = (blockIdx.x * blockDim.x + threadIdx.x) >> 5;  // bs index
    const int b = gw >> 11;
    const int s = gw & 2047;
    const float* sc = g_scale + 2 * 128;
    const float* bi = g_bias + 2 * 128;
#pragma unroll
    for (int j = 0; j < 4; ++j) {
        int o = lane + 32 * j;
        const float4* row = (const float4*)(g_y2 + (size_t)o * NSAMP + gw * NK);
        float scv = sc[o], biv = bi[o];
        float m = -3.4e38f;
#pragma unroll
        for (int q = 0; q < 4; ++q) {
            float4 v4 = row[q];
            float vv[4] = {v4.x, v4.y, v4.z, v4.w};
#pragma unroll
            for (int r = 0; r < 4; ++r) {
                float v = fmaf(vv[r], scv, biv);
                v = (v > 0.0f) ? v : LEAKY * v;
                m = fmaxf(m, v);
            }
        }
        out[OUT_FEAT_OFF + ((size_t)b * 128 + o) * NSP + s] = m;
    }
}

// ---------------- launch ----------------
extern "C" void kernel_launch(void* const* d_in, const int* in_sizes, int n_in,
                              void* d_out, int out_size) {
    (void)in_sizes; (void)n_in; (void)out_size;
    const float* xyz = (const float*)d_in[0];
    const float* pts = (const float*)d_in[1];
    const float* w0 = (const float*)d_in[2];
    const float* w1 = (const float*)d_in[3];
    const float* w2 = (const float*)d_in[4];
    const float* g0 = (const float*)d_in[5];
    const float* b0 = (const float*)d_in[6];
    const float* g1 = (const float*)d_in[7];
    const float* b1 = (const float*)d_in[8];
    const float* g2 = (const float*)d_in[9];
    const float* b2 = (const float*)d_in[10];
    float* out = (float*)d_out;

    const int fps_smem = 3 * NPTS * 4 + 64 * 4 + 16;
    cudaFuncSetAttribute(k_fps, cudaFuncAttributeMaxDynamicSharedMemorySize, fps_smem);
    const int c1_smem = (64 * 64 + 64 * 64 + 2 * 64) * 4;
    const int c2_smem = (64 * 64 + 64 * 128 + 2 * 128) * 4;
    cudaFuncSetAttribute(k_conv<1>, cudaFuncAttributeMaxDynamicSharedMemorySize, c1_smem);
    cudaFuncSetAttribute(k_conv<2>, cudaFuncAttributeMaxDynamicSharedMemorySize, c2_smem);

    k_zero<<<1, 384>>>();
    k_prep<<<(NB * NPTS) / 256, 256>>>(xyz, pts);
    k_fps<<<NB, 1024, fps_smem>>>(xyz, out);
    k_knn<<<(NB * NSP) / 8, 256>>>(xyz);
    k_conv0<<<NSAMP / 64, 128>>>(xyz, w0);
    k_stats<<<1, 128>>>(0, 64, g0, b0);
    k_conv<1><<<NSAMP / 64, 128, c1_smem>>>(w1);
    k_stats<<<1, 128>>>(1, 64, g1, b1);
    k_conv<2><<<NSAMP / 64, 256, c2_smem>>>(w2);
    k_stats<<<1, 128>>>(2, 128, g2, b2);
    k_final<<<(NB * NSP) / 8, 256>>>(out);
}